// round 6
// baseline (speedup 1.0000x reference)
#include <cuda_runtime.h>
#include <cuda_bf16.h>
#include <cstdint>

#define N_NODES 40000
#define N_EDGES 640000
#define D 128
#define TILE_M 64
#define NTILES 626                     // 40064 / 64
#define PADROWS (NTILES * TILE_M)      // 40064

// ---------------------------------------------------------------------------
// Device scratch (zero-initialized at module load; pad rows stay 0 forever)
// ---------------------------------------------------------------------------
__device__ float g_h[(size_t)N_NODES * D];
__device__ float g_part[(size_t)PADROWS * D];   // self-GEMM partial (fp32)
__device__ int   g_deg[N_NODES];                // zeroed by final kernel of each call
__device__ float g_inv[N_NODES];
__device__ int   g_rowoff[N_NODES];
__device__ int   g_cursor[N_NODES];
__device__ int   g_total;                       // zeroed by final kernel of each call
__device__ int   g_csr[N_EDGES];
// bf16 split operand images, row-major [PADROWS][128]
__device__ unsigned short g_Ah_hi[(size_t)PADROWS * D];
__device__ unsigned short g_Ah_lo[(size_t)PADROWS * D];
__device__ unsigned short g_Aa_hi[(size_t)PADROWS * D];
__device__ unsigned short g_Aa_lo[(size_t)PADROWS * D];
// weight images: [layer][hi/lo][n=128][kv=256] (kv<128: Ws^T, kv>=128: Wn^T)
__device__ unsigned short g_Bimg[3][2][128][256];

// ---------------------------------------------------------------------------
// Helpers
// ---------------------------------------------------------------------------
__device__ __forceinline__ void split_bf16(float v, unsigned short& h, unsigned short& l) {
    __nv_bfloat16 hb = __float2bfloat16_rn(v);
    float r = v - __bfloat162float(hb);
    __nv_bfloat16 lb = __float2bfloat16_rn(r);
    h = __bfloat16_as_ushort(hb);
    l = __bfloat16_as_ushort(lb);
}

__device__ __forceinline__ void store_split4(unsigned short* hi, unsigned short* lo,
                                             size_t idx, float4 v) {
    unsigned short h0, h1, h2, h3, l0, l1, l2, l3;
    split_bf16(v.x, h0, l0); split_bf16(v.y, h1, l1);
    split_bf16(v.z, h2, l2); split_bf16(v.w, h3, l3);
    *(uint2*)(hi + idx) = make_uint2((uint32_t)h0 | ((uint32_t)h1 << 16),
                                     (uint32_t)h2 | ((uint32_t)h3 << 16));
    *(uint2*)(lo + idx) = make_uint2((uint32_t)l0 | ((uint32_t)l1 << 16),
                                     (uint32_t)l2 | ((uint32_t)l3 << 16));
}

__device__ __forceinline__ void mma16816(float* c, const uint32_t* a, const uint32_t* b) {
    asm volatile(
        "mma.sync.aligned.m16n8k16.row.col.f32.bf16.bf16.f32 "
        "{%0,%1,%2,%3}, {%4,%5,%6,%7}, {%8,%9}, {%0,%1,%2,%3};"
        : "+f"(c[0]), "+f"(c[1]), "+f"(c[2]), "+f"(c[3])
        : "r"(a[0]), "r"(a[1]), "r"(a[2]), "r"(a[3]), "r"(b[0]), "r"(b[1]));
}

__device__ __forceinline__ uint32_t smem_u32(const void* p) {
    uint32_t a;
    asm("{ .reg .u64 t; cvta.to.shared.u64 t, %1; cvt.u32.u64 %0, t; }" : "=r"(a) : "l"(p));
    return a;
}

__device__ __forceinline__ void cp16(uint32_t s, const void* g) {
    asm volatile("cp.async.cg.shared.global [%0], [%1], 16;" :: "r"(s), "l"(g));
}
#define CP_COMMIT() asm volatile("cp.async.commit_group;" ::: "memory")
#define CP_WAIT(n)  asm volatile("cp.async.wait_group %0;" :: "n"(n) : "memory")

// ---------------------------------------------------------------------------
// SMEM layout for GEMM kernels (words). A: 64 rows x 64 words (+4 pad).
// B: 128 rows x 64 words (+4 pad). hi/lo images each.
// ---------------------------------------------------------------------------
#define RPA 68
#define A_IMG (64 * RPA)                // 4352
#define B_IMG (128 * RPA)               // 8704
#define OFF_SB (2 * A_IMG)              // 8704
#define CORE_WORDS (2 * A_IMG + 2 * B_IMG)   // 26112 words = 104448 B
#define OFF_BIAS_W CORE_WORDS
#define NEIGH_WORDS (CORE_WORDS + 128)       // 104960 B

// ---------------------------------------------------------------------------
// GEMM core: stage A (hi/lo) + B (hi/lo, K=128 half selected by kvbase),
// compute 3-pass split MMA into acc. 8 warps = 2(M) x 4(N), warp tile 32x32.
// ---------------------------------------------------------------------------
__device__ __forceinline__ void gemm_core(
    uint32_t* sm, uint32_t smb, int layer, int kvbase,
    const unsigned short* __restrict__ Ahi_g, const unsigned short* __restrict__ Alo_g,
    size_t row0, float acc[2][4][4])
{
    int tid = threadIdx.x;
    // stage A: 2 imgs x 64 rows x 16 segs (16B) = 2048 cp16
    #pragma unroll
    for (int it = 0; it < 8; it++) {
        int i = tid + it * 256;
        int img = i >> 10, rem = i & 1023;
        int r = rem >> 4, seg = rem & 15;
        const unsigned short* s = (img ? Alo_g : Ahi_g) + (row0 + r) * D + seg * 8;
        cp16(smb + (img * A_IMG + r * RPA + seg * 4) * 4, s);
    }
    // stage B: 2 imgs x 128 rows x 16 segs = 4096 cp16
    #pragma unroll
    for (int it = 0; it < 16; it++) {
        int i = tid + it * 256;
        int img = i >> 11, rem = i & 2047;
        int n = rem >> 4, seg = rem & 15;
        cp16(smb + (OFF_SB + img * B_IMG + n * RPA + seg * 4) * 4,
             &g_Bimg[layer][img][n][kvbase + seg * 8]);
    }
    CP_COMMIT();
    CP_WAIT(0);
    __syncthreads();

    const uint32_t* Ahi = sm;
    const uint32_t* Alo = sm + A_IMG;
    const uint32_t* B0 = sm + OFF_SB;
    const uint32_t* B1 = sm + OFF_SB + B_IMG;
    int wid = tid >> 5, lane = tid & 31;
    int wm = wid >> 2, wn = wid & 3;
    int g = lane >> 2, c = lane & 3;

    #pragma unroll
    for (int kk = 0; kk < 8; kk++) {
        uint32_t ah[2][4], al[2][4], bh[4][2], bl[4][2];
        #pragma unroll
        for (int mf = 0; mf < 2; mf++) {
            int wb = (wm * 32 + mf * 16 + g) * RPA + kk * 8 + c;
            ah[mf][0] = Ahi[wb];
            ah[mf][1] = Ahi[wb + 8 * RPA];
            ah[mf][2] = Ahi[wb + 4];
            ah[mf][3] = Ahi[wb + 8 * RPA + 4];
            al[mf][0] = Alo[wb];
            al[mf][1] = Alo[wb + 8 * RPA];
            al[mf][2] = Alo[wb + 4];
            al[mf][3] = Alo[wb + 8 * RPA + 4];
        }
        #pragma unroll
        for (int nf = 0; nf < 4; nf++) {
            int wb = (wn * 32 + nf * 8 + g) * RPA + kk * 8 + c;
            bh[nf][0] = B0[wb];
            bh[nf][1] = B0[wb + 4];
            bl[nf][0] = B1[wb];
            bl[nf][1] = B1[wb + 4];
        }
        #pragma unroll
        for (int mf = 0; mf < 2; mf++)
            #pragma unroll
            for (int nf = 0; nf < 4; nf++) {
                mma16816(acc[mf][nf], ah[mf], bh[nf]);
                mma16816(acc[mf][nf], ah[mf], bl[nf]);
                mma16816(acc[mf][nf], al[mf], bh[nf]);
            }
    }
}

// ---------------------------------------------------------------------------
// Aggregation body: one warp per dst node, fp32 gather-sum, split-image write.
// ---------------------------------------------------------------------------
__device__ __forceinline__ void agg_body(const float* __restrict__ h, int warp_gid,
                                         int lane) {
    int node = warp_gid;
    if (node >= N_NODES) return;
    int beg = g_rowoff[node];
    int end = beg + g_deg[node];
    const float4* __restrict__ h4 = (const float4*)h;

    float4 acc = make_float4(0.f, 0.f, 0.f, 0.f);
    int i = beg;
    for (; i + 4 <= end; i += 4) {
        int s0 = g_csr[i], s1 = g_csr[i + 1], s2 = g_csr[i + 2], s3 = g_csr[i + 3];
        float4 v0 = h4[s0 * 32 + lane];
        float4 v1 = h4[s1 * 32 + lane];
        float4 v2 = h4[s2 * 32 + lane];
        float4 v3 = h4[s3 * 32 + lane];
        acc.x += (v0.x + v1.x) + (v2.x + v3.x);
        acc.y += (v0.y + v1.y) + (v2.y + v3.y);
        acc.z += (v0.z + v1.z) + (v2.z + v3.z);
        acc.w += (v0.w + v1.w) + (v2.w + v3.w);
    }
    for (; i < end; i++) {
        int s0 = g_csr[i];
        float4 v0 = h4[s0 * 32 + lane];
        acc.x += v0.x; acc.y += v0.y; acc.z += v0.z; acc.w += v0.w;
    }
    float inv = g_inv[node];
    acc.x *= inv; acc.y *= inv; acc.z *= inv; acc.w *= inv;
    store_split4(g_Aa_hi, g_Aa_lo, (size_t)node * D + lane * 4, acc);
}

// ---------------------------------------------------------------------------
// Prep (merged): weight images + x->self images + degree count.
// Requires g_deg, g_total already zero (done by final kernel of previous call;
// module-load zero-init covers the first call).
// ---------------------------------------------------------------------------
__global__ void __launch_bounds__(256) prep_kernel(
    const float* __restrict__ x, const float* __restrict__ ws,
    const float* __restrict__ wn, const int* __restrict__ dst)
{
    int tid = blockIdx.x * 256 + threadIdx.x;      // 0..1279999
    // weight images
    if (tid < 3 * 128 * 256) {
        int l = tid >> 15;
        int rem = tid & 32767;
        int n = rem >> 8;
        int kv = rem & 255;
        float v = (kv < 128) ? ws[l * 16384 + kv * 128 + n]
                             : wn[l * 16384 + (kv - 128) * 128 + n];
        unsigned short h, lo;
        split_bf16(v, h, lo);
        g_Bimg[l][0][n][kv] = h;
        g_Bimg[l][1][n][kv] = lo;
    }
    // degree count
    if (tid < N_EDGES) atomicAdd(&g_deg[dst[tid]], 1);
    // x -> self split images (warp per node; 40000 warps exactly)
    int node = tid >> 5;
    int lane = tid & 31;
    if (node < N_NODES) {
        float4 v = ((const float4*)x)[node * 32 + lane];
        store_split4(g_Ah_hi, g_Ah_lo, (size_t)node * D + lane * 4, v);
    }
}

// 16 nodes per thread -> 2.5K atomics on g_total instead of 40K
__global__ void offsets_kernel() {
    int t = blockIdx.x * 256 + threadIdx.x;        // 0..2559
    int base = t * 16;
    if (base >= N_NODES) return;
    int dloc[16];
    int dsum = 0;
    #pragma unroll
    for (int i = 0; i < 16; i++) {
        int idx = base + i;
        dloc[i] = (idx < N_NODES) ? g_deg[idx] : 0;
        dsum += dloc[i];
    }
    int off = atomicAdd(&g_total, dsum);
    #pragma unroll
    for (int i = 0; i < 16; i++) {
        int idx = base + i;
        if (idx < N_NODES) {
            g_rowoff[idx] = off;
            g_cursor[idx] = off;
            g_inv[idx] = (dloc[i] > 0) ? 1.0f / (float)dloc[i] : 1.0f;
            off += dloc[i];
        }
    }
}

// ---------------------------------------------------------------------------
// Heterogeneous kernel: blocks [0,NTILES) run self-GEMM (part = h @ Ws, fp32
// to g_part); remaining blocks run fill (mode 0, layer 0) or agg (mode 1).
// ---------------------------------------------------------------------------
__global__ void __launch_bounds__(256) hetero_kernel(
    int layer, const float* __restrict__ hsrc,
    const int* __restrict__ src, const int* __restrict__ dst, int mode)
{
    extern __shared__ __align__(16) uint32_t sm[];
    if (blockIdx.x >= NTILES) {
        int bid2 = blockIdx.x - NTILES;
        if (mode == 0) {                           // CSR fill
            int e = bid2 * 256 + threadIdx.x;
            if (e < N_EDGES) {
                int p = atomicAdd(&g_cursor[dst[e]], 1);
                g_csr[p] = src[e];
            }
        } else {                                   // aggregation
            agg_body(hsrc, bid2 * 8 + (threadIdx.x >> 5), threadIdx.x & 31);
        }
        return;
    }

    // self-GEMM tile
    uint32_t smb = smem_u32(sm);
    size_t row0 = (size_t)blockIdx.x * TILE_M;
    float acc[2][4][4];
    #pragma unroll
    for (int mf = 0; mf < 2; mf++)
        #pragma unroll
        for (int nf = 0; nf < 4; nf++)
            #pragma unroll
            for (int k = 0; k < 4; k++) acc[mf][nf][k] = 0.f;

    gemm_core(sm, smb, layer, 0, g_Ah_hi, g_Ah_lo, row0, acc);

    int wid = threadIdx.x >> 5, lane = threadIdx.x & 31;
    int wm = wid >> 2, wn = wid & 3;
    int g = lane >> 2, c = lane & 3;
    #pragma unroll
    for (int mf = 0; mf < 2; mf++) {
        size_t r_lo = row0 + wm * 32 + mf * 16 + g;
        size_t r_hi = r_lo + 8;
        #pragma unroll
        for (int nf = 0; nf < 4; nf++) {
            int col = wn * 32 + nf * 8 + c * 2;
            *(float2*)(g_part + r_lo * D + col) = make_float2(acc[mf][nf][0], acc[mf][nf][1]);
            *(float2*)(g_part + r_hi * D + col) = make_float2(acc[mf][nf][2], acc[mf][nf][3]);
        }
    }
}

// ---------------------------------------------------------------------------
// Standalone aggregation (layer 0: full occupancy, no smem)
// ---------------------------------------------------------------------------
__global__ void __launch_bounds__(256) agg_kernel(const float* __restrict__ h) {
    agg_body(h, (blockIdx.x * blockDim.x + threadIdx.x) >> 5, threadIdx.x & 31);
}

// ---------------------------------------------------------------------------
// Neighbor GEMM + combine: out = g_part + agg @ Wn + b (+ReLU) (+images).
// cleanup=1 (final layer) also zeroes g_deg/g_total for the next call.
// ---------------------------------------------------------------------------
__global__ void __launch_bounds__(256) gemm_neigh_kernel(
    int layer, const float* __restrict__ bias, float* __restrict__ out,
    int do_relu, int write_img, int cleanup)
{
    extern __shared__ __align__(16) uint32_t sm[];
    uint32_t smb = smem_u32(sm);

    if (cleanup) {
        int gid = blockIdx.x * 256 + threadIdx.x;
        if (gid < N_NODES) g_deg[gid] = 0;
        if (gid == 0) g_total = 0;
    }
    if (threadIdx.x < 128) sm[OFF_BIAS_W + threadIdx.x] = __float_as_uint(bias[threadIdx.x]);

    size_t row0 = (size_t)blockIdx.x * TILE_M;
    float acc[2][4][4];
    #pragma unroll
    for (int mf = 0; mf < 2; mf++)
        #pragma unroll
        for (int nf = 0; nf < 4; nf++)
            #pragma unroll
            for (int k = 0; k < 4; k++) acc[mf][nf][k] = 0.f;

    gemm_core(sm, smb, layer, 128, g_Aa_hi, g_Aa_lo, row0, acc);

    const float* bias_sm = (const float*)(sm + OFF_BIAS_W);
    int wid = threadIdx.x >> 5, lane = threadIdx.x & 31;
    int wm = wid >> 2, wn = wid & 3;
    int g = lane >> 2, c = lane & 3;

    #pragma unroll
    for (int mf = 0; mf < 2; mf++) {
        size_t r_lo = row0 + wm * 32 + mf * 16 + g;
        size_t r_hi = r_lo + 8;
        #pragma unroll
        for (int nf = 0; nf < 4; nf++) {
            int col = wn * 32 + nf * 8 + c * 2;
            float b0 = bias_sm[col], b1 = bias_sm[col + 1];
            float2 p0 = *(const float2*)(g_part + r_lo * D + col);
            float2 p1 = *(const float2*)(g_part + r_hi * D + col);
            float v00 = acc[mf][nf][0] + p0.x + b0, v01 = acc[mf][nf][1] + p0.y + b1;
            float v10 = acc[mf][nf][2] + p1.x + b0, v11 = acc[mf][nf][3] + p1.y + b1;
            if (do_relu) {
                v00 = fmaxf(v00, 0.f); v01 = fmaxf(v01, 0.f);
                v10 = fmaxf(v10, 0.f); v11 = fmaxf(v11, 0.f);
            }
            if (r_lo < N_NODES) {
                *(float2*)(out + r_lo * D + col) = make_float2(v00, v01);
                if (write_img) {
                    unsigned short h0, h1, l0, l1;
                    split_bf16(v00, h0, l0); split_bf16(v01, h1, l1);
                    *(uint32_t*)(g_Ah_hi + r_lo * D + col) = (uint32_t)h0 | ((uint32_t)h1 << 16);
                    *(uint32_t*)(g_Ah_lo + r_lo * D + col) = (uint32_t)l0 | ((uint32_t)l1 << 16);
                }
            }
            if (r_hi < N_NODES) {
                *(float2*)(out + r_hi * D + col) = make_float2(v10, v11);
                if (write_img) {
                    unsigned short h0, h1, l0, l1;
                    split_bf16(v10, h0, l0); split_bf16(v11, h1, l1);
                    *(uint32_t*)(g_Ah_hi + r_hi * D + col) = (uint32_t)h0 | ((uint32_t)h1 << 16);
                    *(uint32_t*)(g_Ah_lo + r_hi * D + col) = (uint32_t)l0 | ((uint32_t)l1 << 16);
                }
            }
        }
    }
}

// ---------------------------------------------------------------------------
// Launch
// ---------------------------------------------------------------------------
extern "C" void kernel_launch(void* const* d_in, const int* in_sizes, int n_in,
                              void* d_out, int out_size) {
    const float* x       = (const float*)d_in[0];
    const int*   src     = (const int*)d_in[1];
    const int*   dst     = (const int*)d_in[2];
    const float* w_self  = (const float*)d_in[3];
    const float* w_neigh = (const float*)d_in[4];
    const float* b       = (const float*)d_in[5];
    float*       out     = (float*)d_out;

    cudaFuncSetAttribute(hetero_kernel, cudaFuncAttributeMaxDynamicSharedMemorySize,
                         CORE_WORDS * 4);
    cudaFuncSetAttribute(gemm_neigh_kernel, cudaFuncAttributeMaxDynamicSharedMemorySize,
                         NEIGH_WORDS * 4);

    void* hptr_v = nullptr;
    cudaGetSymbolAddress(&hptr_v, g_h);
    float* hptr = (float*)hptr_v;

    // Prep: weights + x images + degree count (deg pre-zeroed by prior call)
    prep_kernel<<<5000, 256>>>(x, w_self, w_neigh, dst);
    offsets_kernel<<<10, 256>>>();

    // Layer 0: selfGEMM(0) overlapped with CSR fill; then agg(x); then combine
    hetero_kernel<<<NTILES + 2500, 256, CORE_WORDS * 4>>>(0, nullptr, src, dst, 0);
    agg_kernel<<<5000, 256>>>(x);
    gemm_neigh_kernel<<<NTILES, 256, NEIGH_WORDS * 4>>>(0, b, hptr, 1, 1, 0);

    // Layer 1: selfGEMM(1) || agg(g_h); combine
    hetero_kernel<<<NTILES + 5000, 256, CORE_WORDS * 4>>>(1, hptr, src, dst, 1);
    gemm_neigh_kernel<<<NTILES, 256, NEIGH_WORDS * 4>>>(1, b + 128, hptr, 1, 1, 0);

    // Layer 2: selfGEMM(2) || agg(g_h); combine -> out (no relu/images), cleanup
    hetero_kernel<<<NTILES + 5000, 256, CORE_WORDS * 4>>>(2, hptr, src, dst, 1);
    gemm_neigh_kernel<<<NTILES, 256, NEIGH_WORDS * 4>>>(2, b + 256, out, 0, 0, 1);
}

// round 7
// speedup vs baseline: 1.4565x; 1.4565x over previous
#include <cuda_runtime.h>
#include <cuda_bf16.h>
#include <cstdint>

#define N_NODES 40000
#define N_EDGES 640000
#define D 128
#define TILE_M 64
#define NTILES 626                     // 40064 / 64
#define PADROWS (NTILES * TILE_M)      // 40064

// ---------------------------------------------------------------------------
// Device scratch (zero-initialized at module load; pad rows stay 0 forever).
// g_deg / g_total are re-zeroed by the LAST kernel of each launch so the next
// (graph-replayed) call starts clean.
// ---------------------------------------------------------------------------
__device__ float g_h[(size_t)N_NODES * D];
__device__ int   g_deg[N_NODES];
__device__ float g_inv[N_NODES];
__device__ int   g_rowoff[N_NODES];
__device__ int   g_cursor[N_NODES];
__device__ int   g_total;
__device__ int   g_csr[N_EDGES];
// bf16 split operand images, row-major [PADROWS][128]
__device__ unsigned short g_Ah_hi[(size_t)PADROWS * D];
__device__ unsigned short g_Ah_lo[(size_t)PADROWS * D];
__device__ unsigned short g_Aa_hi[(size_t)PADROWS * D];
__device__ unsigned short g_Aa_lo[(size_t)PADROWS * D];
// weight images: [layer][hi/lo][n=128][kv=256] (kv<128: Ws^T, kv>=128: Wn^T)
__device__ unsigned short g_Bimg[3][2][128][256];

// ---------------------------------------------------------------------------
// Helpers
// ---------------------------------------------------------------------------
__device__ __forceinline__ void split_bf16(float v, unsigned short& h, unsigned short& l) {
    __nv_bfloat16 hb = __float2bfloat16_rn(v);
    float r = v - __bfloat162float(hb);
    __nv_bfloat16 lb = __float2bfloat16_rn(r);
    h = __bfloat16_as_ushort(hb);
    l = __bfloat16_as_ushort(lb);
}

__device__ __forceinline__ void store_split4(unsigned short* hi, unsigned short* lo,
                                             size_t idx, float4 v) {
    unsigned short h0, h1, h2, h3, l0, l1, l2, l3;
    split_bf16(v.x, h0, l0); split_bf16(v.y, h1, l1);
    split_bf16(v.z, h2, l2); split_bf16(v.w, h3, l3);
    *(uint2*)(hi + idx) = make_uint2((uint32_t)h0 | ((uint32_t)h1 << 16),
                                     (uint32_t)h2 | ((uint32_t)h3 << 16));
    *(uint2*)(lo + idx) = make_uint2((uint32_t)l0 | ((uint32_t)l1 << 16),
                                     (uint32_t)l2 | ((uint32_t)l3 << 16));
}

__device__ __forceinline__ void mma16816(float* c, const uint32_t* a, const uint32_t* b) {
    asm volatile(
        "mma.sync.aligned.m16n8k16.row.col.f32.bf16.bf16.f32 "
        "{%0,%1,%2,%3}, {%4,%5,%6,%7}, {%8,%9}, {%0,%1,%2,%3};"
        : "+f"(c[0]), "+f"(c[1]), "+f"(c[2]), "+f"(c[3])
        : "r"(a[0]), "r"(a[1]), "r"(a[2]), "r"(a[3]), "r"(b[0]), "r"(b[1]));
}

__device__ __forceinline__ void ldsm_x4(uint32_t* r, uint32_t addr) {
    asm volatile("ldmatrix.sync.aligned.m8n8.x4.shared.b16 {%0,%1,%2,%3}, [%4];"
                 : "=r"(r[0]), "=r"(r[1]), "=r"(r[2]), "=r"(r[3]) : "r"(addr));
}

__device__ __forceinline__ void ldsm_x2(uint32_t* r, uint32_t addr) {
    asm volatile("ldmatrix.sync.aligned.m8n8.x2.shared.b16 {%0,%1}, [%2];"
                 : "=r"(r[0]), "=r"(r[1]) : "r"(addr));
}

__device__ __forceinline__ uint32_t smem_u32(const void* p) {
    uint32_t a;
    asm("{ .reg .u64 t; cvta.to.shared.u64 t, %1; cvt.u32.u64 %0, t; }" : "=r"(a) : "l"(p));
    return a;
}

__device__ __forceinline__ void cp16(uint32_t s, const void* g) {
    asm volatile("cp.async.cg.shared.global [%0], [%1], 16;" :: "r"(s), "l"(g));
}
#define CP_COMMIT() asm volatile("cp.async.commit_group;" ::: "memory")
#define CP_WAIT(n)  asm volatile("cp.async.wait_group %0;" :: "n"(n) : "memory")

// ---------------------------------------------------------------------------
// Prep (merged): weight images + x->self images + degree count.
// g_deg/g_total already zero (zeroed by prior call's last kernel / load-init).
// ---------------------------------------------------------------------------
__global__ void __launch_bounds__(256) prep_kernel(
    const float* __restrict__ x, const float* __restrict__ ws,
    const float* __restrict__ wn, const int* __restrict__ dst)
{
    int tid = blockIdx.x * 256 + threadIdx.x;      // 0..1279999
    if (tid < 3 * 128 * 256) {                     // weight images
        int l = tid >> 15;
        int rem = tid & 32767;
        int n = rem >> 8;
        int kv = rem & 255;
        float v = (kv < 128) ? ws[l * 16384 + kv * 128 + n]
                             : wn[l * 16384 + (kv - 128) * 128 + n];
        unsigned short h, lo;
        split_bf16(v, h, lo);
        g_Bimg[l][0][n][kv] = h;
        g_Bimg[l][1][n][kv] = lo;
    }
    if (tid < N_EDGES) atomicAdd(&g_deg[dst[tid]], 1);   // degree count
    int node = tid >> 5;                           // x -> self split images
    int lane = tid & 31;
    if (node < N_NODES) {
        float4 v = ((const float4*)x)[node * 32 + lane];
        store_split4(g_Ah_hi, g_Ah_lo, (size_t)node * D + lane * 4, v);
    }
}

// 16 nodes per thread -> 2.5K atomics on g_total instead of 40K
__global__ void offsets_kernel() {
    int t = blockIdx.x * 256 + threadIdx.x;        // 0..2559
    int base = t * 16;
    if (base >= N_NODES) return;
    int dloc[16];
    int dsum = 0;
    #pragma unroll
    for (int i = 0; i < 16; i++) {
        int idx = base + i;
        dloc[i] = (idx < N_NODES) ? g_deg[idx] : 0;
        dsum += dloc[i];
    }
    int off = atomicAdd(&g_total, dsum);
    #pragma unroll
    for (int i = 0; i < 16; i++) {
        int idx = base + i;
        if (idx < N_NODES) {
            g_rowoff[idx] = off;
            g_cursor[idx] = off;
            g_inv[idx] = (dloc[i] > 0) ? 1.0f / (float)dloc[i] : 1.0f;
            off += dloc[i];
        }
    }
}

__global__ void fill_kernel(const int* __restrict__ src, const int* __restrict__ dst) {
    int e = blockIdx.x * blockDim.x + threadIdx.x;
    if (e < N_EDGES) {
        int p = atomicAdd(&g_cursor[dst[e]], 1);
        g_csr[p] = src[e];
    }
}

// ---------------------------------------------------------------------------
// Aggregation: one warp per dst node; fp32 gather-sum from L2 (4-deep MLP);
// writes split bf16 agg images. (At its LTS roofline — leave alone.)
// ---------------------------------------------------------------------------
__global__ void __launch_bounds__(256) agg_kernel(const float* __restrict__ h) {
    int node = (blockIdx.x * blockDim.x + threadIdx.x) >> 5;
    int lane = threadIdx.x & 31;
    if (node >= N_NODES) return;
    int beg = g_rowoff[node];
    int end = beg + g_deg[node];
    const float4* __restrict__ h4 = (const float4*)h;

    float4 acc = make_float4(0.f, 0.f, 0.f, 0.f);
    int i = beg;
    for (; i + 4 <= end; i += 4) {
        int s0 = g_csr[i], s1 = g_csr[i + 1], s2 = g_csr[i + 2], s3 = g_csr[i + 3];
        float4 v0 = h4[s0 * 32 + lane];
        float4 v1 = h4[s1 * 32 + lane];
        float4 v2 = h4[s2 * 32 + lane];
        float4 v3 = h4[s3 * 32 + lane];
        acc.x += (v0.x + v1.x) + (v2.x + v3.x);
        acc.y += (v0.y + v1.y) + (v2.y + v3.y);
        acc.z += (v0.z + v1.z) + (v2.z + v3.z);
        acc.w += (v0.w + v1.w) + (v2.w + v3.w);
    }
    for (; i < end; i++) {
        int s0 = g_csr[i];
        float4 v0 = h4[s0 * 32 + lane];
        acc.x += v0.x; acc.y += v0.y; acc.z += v0.z; acc.w += v0.w;
    }
    float inv = g_inv[node];
    acc.x *= inv; acc.y *= inv; acc.z *= inv; acc.w *= inv;
    store_split4(g_Aa_hi, g_Aa_lo, (size_t)node * D + lane * 4, acc);
}

// ---------------------------------------------------------------------------
// mma.sync bf16-split GEMM (R5 structure + ldmatrix operand loads).
// M=64 tiles (626 CTAs), A fully SMEM-resident, B double-buffered via
// cp.async in 8 k-chunks of 32. out[64x128] = [h|agg] @ [Ws;Wn] + b (+ReLU).
// 8 warps: 2(M) x 4(N); warp tile 32x32.
// ---------------------------------------------------------------------------
#define RPA 68                          // A row stride (words): 64 data + 4 pad
#define RPB 20                          // B row stride (words): 16 data + 4 pad
#define A_IMG (64 * RPA)                // 4352 words per image
#define OFF_AS 0                        // self hi; lo at +A_IMG
#define OFF_AA (2 * A_IMG)              // agg hi; lo at +A_IMG
#define B_IMG (128 * RPB)               // 2560 words per image
#define OFF_B  (4 * A_IMG)              // [buf][img]: + buf*2*B_IMG + img*B_IMG
#define OFF_BIAS (4 * A_IMG + 4 * B_IMG)
#define SMEM_WORDS (OFF_BIAS + 128)     // 27776 words = 111104 B

__global__ void __launch_bounds__(256) mma_gemm_kernel(
    int layer, const float* __restrict__ bias, float* __restrict__ out,
    int do_relu, int write_img, int cleanup)
{
    extern __shared__ __align__(16) uint32_t sm[];
    uint32_t smb = smem_u32(sm);

    int tid = threadIdx.x;
    int wid = tid >> 5, lane = tid & 31;
    int wm = wid >> 2;        // 0..1 -> m base = wm*32
    int wn = wid & 3;         // 0..3 -> n base = wn*32
    int g = lane >> 2;        // 0..7
    int c = lane & 3;         // 0..3
    size_t row0 = (size_t)blockIdx.x * TILE_M;

    if (cleanup) {            // zero deg/total for the NEXT launch (replay-safe)
        int gid = blockIdx.x * 256 + tid;
        if (gid < N_NODES) g_deg[gid] = 0;
        if (gid == 0) g_total = 0;
    }
    if (tid < 128) sm[OFF_BIAS + tid] = __float_as_uint(bias[tid]);

    float acc[2][4][4];
    #pragma unroll
    for (int mf = 0; mf < 2; mf++)
        #pragma unroll
        for (int nf = 0; nf < 4; nf++)
            #pragma unroll
            for (int k = 0; k < 4; k++) acc[mf][nf][k] = 0.f;

    // --- stage all of A (4 images x 64 rows x 16 segs of 16B) ---
    {
        const unsigned short* srcs[4] = {g_Ah_hi, g_Ah_lo, g_Aa_hi, g_Aa_lo};
        const uint32_t dsts[4] = {OFF_AS, OFF_AS + A_IMG, OFF_AA, OFF_AA + A_IMG};
        #pragma unroll
        for (int it = 0; it < 16; it++) {
            int i = tid + it * 256;       // 0..4095
            int img = i >> 10;
            int rem = i & 1023;
            int r = rem >> 4;
            int seg = rem & 15;
            cp16(smb + (dsts[img] + r * RPA + seg * 4) * 4,
                 srcs[img] + (row0 + r) * D + seg * 8);
        }
    }
    // --- stage B chunk into buf ---
    auto stageB = [&](int ch, int buf) {
        #pragma unroll
        for (int it = 0; it < 4; it++) {
            int i = tid + it * 256;       // 0..1023
            int img = i >> 9;
            int rem = i & 511;
            int n = rem >> 2;
            int seg = rem & 3;
            cp16(smb + (OFF_B + buf * 2 * B_IMG + img * B_IMG + n * RPB + seg * 4) * 4,
                 &g_Bimg[layer][img][n][ch * 32 + seg * 8]);
        }
    };

    stageB(0, 0);
    CP_COMMIT();

    // ldmatrix per-thread invariant offsets (words)
    uint32_t aoff = (uint32_t)(wm * 32 + (lane & 15)) * RPA + ((lane >> 4) << 2);
    uint32_t boff = (uint32_t)(wn * 32 + (lane & 7)) * RPB + (((lane >> 3) & 1) << 2);

    for (int ch = 0; ch < 8; ch++) {
        int buf = ch & 1;
        if (ch < 7) {
            stageB(ch + 1, buf ^ 1);
            CP_COMMIT();
            CP_WAIT(1);
        } else {
            CP_WAIT(0);
        }
        __syncthreads();

        uint32_t baseA = (ch < 4) ? OFF_AS : OFF_AA;
        uint32_t baseB = OFF_B + buf * 2 * B_IMG;
        int chm = (ch & 3) * 16;          // word base within A row

        #pragma unroll
        for (int kk = 0; kk < 2; kk++) {
            uint32_t ah[2][4], al[2][4], bh[4][2], bl[4][2];
            #pragma unroll
            for (int mf = 0; mf < 2; mf++) {
                uint32_t wo = baseA + aoff + (uint32_t)(mf * 16) * RPA + chm + kk * 8;
                ldsm_x4(ah[mf], smb + wo * 4);
                ldsm_x4(al[mf], smb + (wo + A_IMG) * 4);
            }
            #pragma unroll
            for (int nf = 0; nf < 4; nf++) {
                uint32_t wo = baseB + boff + (uint32_t)(nf * 8) * RPB + kk * 8;
                ldsm_x2(bh[nf], smb + wo * 4);
                ldsm_x2(bl[nf], smb + (wo + B_IMG) * 4);
            }
            #pragma unroll
            for (int mf = 0; mf < 2; mf++)
                #pragma unroll
                for (int nf = 0; nf < 4; nf++) {
                    mma16816(acc[mf][nf], ah[mf], bh[nf]);
                    mma16816(acc[mf][nf], ah[mf], bl[nf]);
                    mma16816(acc[mf][nf], al[mf], bh[nf]);
                }
        }
        __syncthreads();
    }

    // --- epilogue: bias + relu, write fp32 out (+ next-layer self images) ---
    const float* bias_sm = (const float*)(sm + OFF_BIAS);
    #pragma unroll
    for (int mf = 0; mf < 2; mf++) {
        size_t r_lo = row0 + wm * 32 + mf * 16 + g;
        size_t r_hi = r_lo + 8;
        #pragma unroll
        for (int nf = 0; nf < 4; nf++) {
            int col = wn * 32 + nf * 8 + c * 2;
            float b0 = bias_sm[col], b1 = bias_sm[col + 1];
            float v00 = acc[mf][nf][0] + b0, v01 = acc[mf][nf][1] + b1;
            float v10 = acc[mf][nf][2] + b0, v11 = acc[mf][nf][3] + b1;
            if (do_relu) {
                v00 = fmaxf(v00, 0.f); v01 = fmaxf(v01, 0.f);
                v10 = fmaxf(v10, 0.f); v11 = fmaxf(v11, 0.f);
            }
            if (r_lo < N_NODES) {
                *(float2*)(out + r_lo * D + col) = make_float2(v00, v01);
                if (write_img) {
                    unsigned short h0, h1, l0, l1;
                    split_bf16(v00, h0, l0); split_bf16(v01, h1, l1);
                    *(uint32_t*)(g_Ah_hi + r_lo * D + col) = (uint32_t)h0 | ((uint32_t)h1 << 16);
                    *(uint32_t*)(g_Ah_lo + r_lo * D + col) = (uint32_t)l0 | ((uint32_t)l1 << 16);
                }
            }
            if (r_hi < N_NODES) {
                *(float2*)(out + r_hi * D + col) = make_float2(v10, v11);
                if (write_img) {
                    unsigned short h0, h1, l0, l1;
                    split_bf16(v10, h0, l0); split_bf16(v11, h1, l1);
                    *(uint32_t*)(g_Ah_hi + r_hi * D + col) = (uint32_t)h0 | ((uint32_t)h1 << 16);
                    *(uint32_t*)(g_Ah_lo + r_hi * D + col) = (uint32_t)l0 | ((uint32_t)l1 << 16);
                }
            }
        }
    }
}

// ---------------------------------------------------------------------------
// Launch
// ---------------------------------------------------------------------------
extern "C" void kernel_launch(void* const* d_in, const int* in_sizes, int n_in,
                              void* d_out, int out_size) {
    const float* x       = (const float*)d_in[0];
    const int*   src     = (const int*)d_in[1];
    const int*   dst     = (const int*)d_in[2];
    const float* w_self  = (const float*)d_in[3];
    const float* w_neigh = (const float*)d_in[4];
    const float* b       = (const float*)d_in[5];
    float*       out     = (float*)d_out;

    cudaFuncSetAttribute(mma_gemm_kernel, cudaFuncAttributeMaxDynamicSharedMemorySize,
                         SMEM_WORDS * 4);

    void* hptr_v = nullptr;
    cudaGetSymbolAddress(&hptr_v, g_h);
    float* hptr = (float*)hptr_v;

    // Prep: weights + x images + degree count (deg pre-zeroed), then CSR
    prep_kernel<<<5000, 256>>>(x, w_self, w_neigh, dst);
    offsets_kernel<<<10, 256>>>();
    fill_kernel<<<2500, 256>>>(src, dst);

    // Layer 0
    agg_kernel<<<5000, 256>>>(x);
    mma_gemm_kernel<<<NTILES, 256, SMEM_WORDS * 4>>>(0, b, hptr, 1, 1, 0);
    // Layer 1
    agg_kernel<<<5000, 256>>>(hptr);
    mma_gemm_kernel<<<NTILES, 256, SMEM_WORDS * 4>>>(1, b + 128, hptr, 1, 1, 0);
    // Layer 2 (cleanup zeroes deg/total for next launch)
    agg_kernel<<<5000, 256>>>(hptr);
    mma_gemm_kernel<<<NTILES, 256, SMEM_WORDS * 4>>>(2, b + 256, out, 0, 0, 1);
}